// round 11
// baseline (speedup 1.0000x reference)
#include <cuda_runtime.h>
#include <cstdint>

// ---------------------------------------------------------------------------
// MoE MLP, routed (top-k) formulation on legacy mma.sync tf32 HMMA
// (tcgen05 unavailable: harness compiles via non-'a' compute_103 PTX).
//
//   route:  per-expert compact token lists from probs>0 (TOPK=2 of E=4)
//   GEMM1:  a_e = gelu( X[list_e] @ W1[e] ) * probs[list_e,e]   (tf32-rounded)
//   GEMM2:  y_e = a_e @ W2[e]
//   combine: out[t] = resid[t] + sum_{e in topk(t)} y_e[slot(t,e)]
//
// R11: persistent scheduling reverted (R10 regression: occ-1 GEMM1 is
// barrier-bubble-bound, tensor 47.5%, issue 29%). GEMM1 keeps 192x256/2x4
// but now PAIRED K-chunks: one wait+syncthreads per 64 K (4 sub-buffers,
// 224.8KB smem) -> half the barrier bubbles. GEMM2 non-persistent grid(8,44)
// (nb = blockIdx.x fastest -> c1p A-panel L2 sharing) with the 192x128 occ-2
// retile (wf/MMA 1.25, B re-read 6x).
// ---------------------------------------------------------------------------

static constexpr int T_TOK = 2048;   // S*B
static constexpr int HID   = 1024;   // H
static constexpr int FFN   = 4096;   // F
static constexpr int NEXP  = 4;      // E
static constexpr int EF    = NEXP * FFN;  // 16384

static constexpr int CAP  = 2112;    // per-expert row capacity (192*11)

// static device scratch (no allocation allowed)
__device__ float g_xr  [(size_t)T_TOK * HID];      //   8 MB rounded X
__device__ float g_w1t [(size_t)EF * HID];         //  67 MB W1^T [e*F+f][h]
__device__ float g_w2t [(size_t)HID * EF];         //  67 MB W2^T [h][e*F+f]
__device__ float g_c1p [(size_t)NEXP * CAP * FFN]; // 138 MB compact act
__device__ float g_y   [(size_t)NEXP * CAP * HID]; //  35 MB compact y
__device__ int   g_idx [NEXP * CAP];               // expert -> token list
__device__ int   g_slot[T_TOK * NEXP];             // (t,e) -> slot
__device__ int   g_cnt [NEXP];

// ---------------------------------------------------------------------------
// helpers
// ---------------------------------------------------------------------------
__device__ __forceinline__ uint32_t smem_u32(const void* p) {
    uint32_t a;
    asm("{ .reg .u64 t; cvta.to.shared.u64 t, %1; cvt.u32.u64 %0, t; }"
        : "=r"(a) : "l"(p));
    return a;
}

__device__ __forceinline__ float to_tf32(float x) {
    uint32_t u;
    asm("cvt.rna.tf32.f32 %0, %1;" : "=r"(u) : "f"(x));
    return __uint_as_float(u);
}

__device__ __forceinline__ uint32_t sw128(uint32_t off) {
    return off ^ ((off >> 3) & 0x70);
}

__device__ __forceinline__ void cpa16(uint32_t dst, const void* src) {
    asm volatile("cp.async.cg.shared.global [%0], [%1], 16;"
                 :: "r"(dst), "l"(src) : "memory");
}

__device__ __forceinline__ void ldsm4(uint32_t* d, uint32_t addr) {
    asm volatile("ldmatrix.sync.aligned.m8n8.x4.shared.b16 {%0,%1,%2,%3}, [%4];"
                 : "=r"(d[0]), "=r"(d[1]), "=r"(d[2]), "=r"(d[3]) : "r"(addr));
}

__device__ __forceinline__ void mma8(float* c, const uint32_t* a,
                                     uint32_t b0, uint32_t b1) {
    asm volatile(
        "mma.sync.aligned.m16n8k8.row.col.f32.tf32.tf32.f32 "
        "{%0,%1,%2,%3}, {%4,%5,%6,%7}, {%8,%9}, {%0,%1,%2,%3};"
        : "+f"(c[0]), "+f"(c[1]), "+f"(c[2]), "+f"(c[3])
        : "r"(a[0]), "r"(a[1]), "r"(a[2]), "r"(a[3]), "r"(b0), "r"(b1));
}

__device__ __forceinline__ float gelu_exact(float x) {
    return 0.5f * x * (1.0f + erff(x * 0.70710678118654752f));
}

// ---------------------------------------------------------------------------
// merged operand prep: one launch, three independent DRAM-bound jobs overlap.
//   blocks [0, 4096):        W1 [E,H,F] -> w1t [E*F][H]   (transpose + round)
//   blocks [4096, 8192):     W2 [EF,H]  -> w2t [H][EF]    (transpose + round)
//   blocks [8192, 10240):    X round to tf32 grid
// ---------------------------------------------------------------------------
__device__ __forceinline__ void tr_tile(const float* __restrict__ in,
                                        float* __restrict__ out,
                                        int R, int C, int bx, int by, int bz,
                                        float (*tile)[68], int tid) {
    size_t base = (size_t)bz * R * C;
    int c0 = bx << 6, r0 = by << 6;
    int tx = tid & 15, ty = tid >> 4;              // 16 x 16
    #pragma unroll
    for (int i = 0; i < 4; i++) {
        int rr = ty + (i << 4);
        float4 v = *(const float4*)&in[base + (size_t)(r0 + rr) * C + c0 + (tx << 2)];
        tile[(tx << 2) + 0][rr] = to_tf32(v.x);
        tile[(tx << 2) + 1][rr] = to_tf32(v.y);
        tile[(tx << 2) + 2][rr] = to_tf32(v.z);
        tile[(tx << 2) + 3][rr] = to_tf32(v.w);
    }
    __syncthreads();
    #pragma unroll
    for (int i = 0; i < 4; i++) {
        int cc = ty + (i << 4);
        float4 w = *(const float4*)&tile[cc][tx << 2];
        *(float4*)&out[base + (size_t)(c0 + cc) * R + r0 + (tx << 2)] = w;
    }
}

__global__ void prep(const float* __restrict__ w1, float* __restrict__ w1t,
                     const float* __restrict__ w2, float* __restrict__ w2t,
                     const float* __restrict__ x,  float* __restrict__ xr) {
    __shared__ float tile[64][68];
    const int b   = blockIdx.x;
    const int tid = threadIdx.x;
    if (b < 4096) {                               // W1 transpose (per expert)
        int e   = b >> 10;                        // 1024 blocks / expert
        int rem = b & 1023;
        tr_tile(w1, w1t, HID, FFN, rem & 63, rem >> 6, e, tile, tid);
    } else if (b < 8192) {                        // W2 transpose
        int rem = b - 4096;                       // bx in [0,16), by in [0,256)
        tr_tile(w2, w2t, EF, HID, rem & 15, rem >> 4, 0, tile, tid);
    } else {                                      // X rounding
        int i = (b - 8192) * 256 + tid;           // float4 index
        float4 v = ((const float4*)x)[i];
        v.x = to_tf32(v.x); v.y = to_tf32(v.y);
        v.z = to_tf32(v.z); v.w = to_tf32(v.w);
        ((float4*)xr)[i] = v;
    }
}

// ---------------------------------------------------------------------------
// routing (zero every launch: graph replay must be stateless)
// ---------------------------------------------------------------------------
__global__ void route_zero(int* idx, int* cnt) {
    int i = blockIdx.x * 256 + threadIdx.x;
    if (i < NEXP * CAP) idx[i] = 0;
    if (i < NEXP) cnt[i] = 0;
}

__global__ void route_build(const float* __restrict__ probs,
                            int* idx, int* slot, int* cnt) {
    int t = blockIdx.x * 256 + threadIdx.x;
    if (t >= T_TOK) return;
    #pragma unroll
    for (int e = 0; e < NEXP; e++) {
        if (probs[t * NEXP + e] > 0.0f) {
            int pos = atomicAdd(&cnt[e], 1);
            idx[e * CAP + pos] = t;
            slot[t * NEXP + e] = pos;
        }
    }
}

// combine: out[t] = resid[t] + sum_e (probs>0) y[e][slot]
__global__ void combine(const float* __restrict__ y,
                        const float* __restrict__ probs,
                        const int* __restrict__ slot,
                        const float* __restrict__ resid,
                        float* __restrict__ out) {
    int t = blockIdx.x;
    int j = threadIdx.x;                          // 256 -> float4 over HID
    float4 acc = ((const float4*)resid)[t * (HID / 4) + j];
    #pragma unroll
    for (int e = 0; e < NEXP; e++) {
        if (probs[t * NEXP + e] > 0.0f) {
            int s = slot[t * NEXP + e];
            float4 v = ((const float4*)y)[((size_t)e * CAP + s) * (HID / 4) + j];
            acc.x += v.x; acc.y += v.y; acc.z += v.z; acc.w += v.w;
        }
    }
    ((float4*)out)[t * (HID / 4) + j] = acc;
}

// ---------------------------------------------------------------------------
// Routed GEMM. CTA tile BMT x BNT, warp grid 2 x WNW (warp tile (BMT/2) x 64),
// BK=32 sub-chunks grouped PAIR at a time: ONE wait+__syncthreads per PAIR
// chunks, SB = STAGES*PAIR sub-buffers. grid (nb, e*TPE + mtile): blockIdx.x
// = n-block varies fastest so CTAs sharing an A panel are launch-adjacent
// (L2 reuse). CTAs past cnt[e] exit.
// MODE 0 (fc1): A rows gathered via token list; epi gelu*probs -> c1p (tf32).
// MODE 1 (fc2): A compact c1p rows; epi plain store -> y.
// ---------------------------------------------------------------------------
template<int MODE, int BMT, int BNT, int WNW, int STAGES, int PAIR, int TPE, int OCC>
__global__ void __launch_bounds__(64 * WNW, OCC)
moe_gemm(const float* __restrict__ A,     // MODE0: g_xr [T,H]; MODE1: g_c1p
         const float* __restrict__ Bt,    // MODE0: g_w1t [EF][H]; MODE1: g_w2t [H][EF]
         const float* __restrict__ probs, // [T,E]
         const int* __restrict__ idx,
         const int* __restrict__ cnt,
         float* __restrict__ Cout,        // MODE0: g_c1p; MODE1: g_y
         int K)                           // MODE0: HID; MODE1: FFN
{
    constexpr int THREADS = 64 * WNW;
    constexpr int WM      = BMT / 2;      // warp tile M
    constexpr int MT      = WM / 16;
    constexpr int NT      = 8;            // warp tile N = 64
    constexpr int A_BYTES = BMT * 128;
    constexpr int B_BYTES = BNT * 128;
    constexpr int STAGE   = A_BYTES + B_BYTES;
    constexpr int SB      = STAGES * PAIR;      // sub-buffers (power of two)

    extern __shared__ __align__(128) char smem[];
    const uint32_t sb = smem_u32(smem);
    int* s_token = (int*)(smem + SB * STAGE);

    const int e    = blockIdx.y / TPE;
    const int tile = blockIdx.y % TPE;
    if (tile * BMT >= cnt[e]) return;

    const int tid  = threadIdx.x;
    const int wid  = tid >> 5;
    const int lane = tid & 31;
    const int wm   = wid / WNW;
    const int wn   = wid % WNW;
    const int n0   = blockIdx.x * BNT;
    const int row_base = e * CAP + tile * BMT;

    if (MODE == 0) {
        for (int i = tid; i < BMT; i += THREADS) s_token[i] = idx[row_base + i];
    }
    __syncthreads();

    const int CCH = K / 32;               // 32-wide sub-chunks
    const int PP  = CCH / PAIR;           // pipeline steps

    auto issue = [&](int c, int s) {
        uint32_t dA = sb + (uint32_t)s * STAGE;
        uint32_t dB = dA + A_BYTES;
        const int k0 = c * 32;
        #pragma unroll
        for (int i = 0; i < BMT * 8 / THREADS; i++) {   // A rows x 2 x 16B
            int id2 = tid + i * THREADS;
            int row = id2 >> 3, cb = (id2 & 7) << 4;
            const float* asrc;
            if (MODE == 0)
                asrc = A + (size_t)s_token[row] * K + k0 + (cb >> 2);
            else
                asrc = A + (size_t)(row_base + row) * K + k0 + (cb >> 2);
            cpa16(dA + sw128((uint32_t)(row * 128 + cb)), asrc);
        }
        #pragma unroll
        for (int i = 0; i < BNT * 8 / THREADS; i++) {   // B rows K-contig
            int id2 = tid + i * THREADS;
            int row = id2 >> 3, cb = (id2 & 7) << 4;
            const float* bsrc;
            if (MODE == 0)   // w1t rows e*F + n, stride K (=HID)
                bsrc = Bt + (size_t)(e * FFN + n0 + row) * K + k0 + (cb >> 2);
            else             // w2t rows n (stride EF), expert cols e*F + k
                bsrc = Bt + (size_t)(n0 + row) * EF + e * FFN + k0 + (cb >> 2);
            cpa16(dB + sw128((uint32_t)(row * 128 + cb)), bsrc);
        }
    };

    // prologue: first STAGES-1 pairs, one commit group per pair
    #pragma unroll
    for (int s = 0; s < STAGES - 1; s++) {
        #pragma unroll
        for (int q = 0; q < PAIR; q++) issue(s * PAIR + q, s * PAIR + q);
        asm volatile("cp.async.commit_group;" ::: "memory");
    }

    float acc[MT][NT][4];
    #pragma unroll
    for (int mt = 0; mt < MT; mt++)
        #pragma unroll
        for (int nt = 0; nt < NT; nt++)
            #pragma unroll
            for (int i = 0; i < 4; i++) acc[mt][nt][i] = 0.0f;

    const int g = lane >> 3, r = lane & 7;

    #pragma unroll 1
    for (int p = 0; p < PP; p++) {
        asm volatile("cp.async.wait_group %0;" :: "n"(STAGES - 2));
        __syncthreads();
        if (p + STAGES - 1 < PP) {
            #pragma unroll
            for (int q = 0; q < PAIR; q++) {
                int c = (p + STAGES - 1) * PAIR + q;
                issue(c, c & (SB - 1));
            }
        }
        asm volatile("cp.async.commit_group;" ::: "memory");  // uniform count

        #pragma unroll
        for (int q = 0; q < PAIR; q++) {
            const int c = p * PAIR + q;
            const uint32_t sA  = sb + (uint32_t)(c & (SB - 1)) * STAGE;
            const uint32_t sBm = sA + A_BYTES;

            #pragma unroll
            for (int ks = 0; ks < 4; ks++) {
                uint32_t bf[NT * 2];
                #pragma unroll
                for (int pp2 = 0; pp2 < NT / 2; pp2++) {
                    int brow = wn * 64 + pp2 * 16 + ((g >> 1) << 3) + r;
                    int bcol = ks * 32 + ((g & 1) << 4);
                    ldsm4(&bf[4 * pp2], sBm + sw128((uint32_t)(brow * 128 + bcol)));
                }
                uint32_t af[2][4];
                {
                    int arow = wm * WM + ((g & 1) << 3) + r;
                    int acol = ks * 32 + ((g >> 1) << 4);
                    ldsm4(af[0], sA + sw128((uint32_t)(arow * 128 + acol)));
                }
                #pragma unroll
                for (int mt = 0; mt < MT; mt++) {
                    if (mt + 1 < MT) {
                        int arow = wm * WM + (mt + 1) * 16 + ((g & 1) << 3) + r;
                        int acol = ks * 32 + ((g >> 1) << 4);
                        ldsm4(af[(mt + 1) & 1], sA + sw128((uint32_t)(arow * 128 + acol)));
                    }
                    #pragma unroll
                    for (int nt = 0; nt < NT; nt++)
                        mma8(acc[mt][nt], af[mt & 1], bf[nt * 2], bf[nt * 2 + 1]);
                }
            }
        }
    }

    // ---------------- epilogue ----------------
    const int qr = lane >> 2, rm = lane & 3;
    const int ldc = (MODE == 0) ? FFN : HID;

    #pragma unroll
    for (int mt = 0; mt < MT; mt++) {
        const int lr0 = wm * WM + mt * 16 + qr;
        const int lr1 = lr0 + 8;
        float p0 = 1.0f, p1 = 1.0f;
        if (MODE == 0) {
            p0 = probs[s_token[lr0] * NEXP + e];
            p1 = probs[s_token[lr1] * NEXP + e];
        }
        #pragma unroll
        for (int nt = 0; nt < NT; nt++) {
            const int col = n0 + wn * 64 + nt * 8 + (rm << 1);
            float2 v0, v1;
            if (MODE == 0) {
                v0.x = to_tf32(gelu_exact(acc[mt][nt][0]) * p0);
                v0.y = to_tf32(gelu_exact(acc[mt][nt][1]) * p0);
                v1.x = to_tf32(gelu_exact(acc[mt][nt][2]) * p1);
                v1.y = to_tf32(gelu_exact(acc[mt][nt][3]) * p1);
            } else {
                v0.x = acc[mt][nt][0]; v0.y = acc[mt][nt][1];
                v1.x = acc[mt][nt][2]; v1.y = acc[mt][nt][3];
            }
            *(float2*)&Cout[(size_t)(row_base + lr0) * ldc + col] = v0;
            *(float2*)&Cout[(size_t)(row_base + lr1) * ldc + col] = v1;
        }
    }
}

// ---------------------------------------------------------------------------
// launch
// ---------------------------------------------------------------------------
extern "C" void kernel_launch(void* const* d_in, const int* in_sizes, int n_in,
                              void* d_out, int out_size) {
    const float* x     = (const float*)d_in[0];   // hidden_states [T,H]
    const float* resid = (const float*)d_in[1];   // mlp_residual  [T,H]
    const float* probs = (const float*)d_in[2];   // probs [T,E] (masked)
    // d_in[3] = routing_map (unused: probs>0 is the same mask, dtype-safe)
    const float* w1    = (const float*)d_in[4];   // [E,H,F]
    const float* w2    = (const float*)d_in[5];   // [E,F,H]
    float* out = (float*)d_out;

    float *xr, *w1t, *w2t, *c1p, *yp;
    int *idxp, *slotp, *cntp;
    cudaGetSymbolAddress((void**)&xr,   g_xr);
    cudaGetSymbolAddress((void**)&w1t,  g_w1t);
    cudaGetSymbolAddress((void**)&w2t,  g_w2t);
    cudaGetSymbolAddress((void**)&c1p,  g_c1p);
    cudaGetSymbolAddress((void**)&yp,   g_y);
    cudaGetSymbolAddress((void**)&idxp, g_idx);
    cudaGetSymbolAddress((void**)&slotp, g_slot);
    cudaGetSymbolAddress((void**)&cntp, g_cnt);

    // GEMM1: 192x256, 2x4 warps, STAGES=2 of PAIR=2 (4 sub-bufs), occ 1.
    // One barrier per 64 K. smem = 4*57344 + 768 = 230144 B (224.75 KB).
    constexpr int SMEM1 = 4 * (192 * 128 + 256 * 128) + 192 * 4;
    // GEMM2: 192x128, 2x2 warps (96x64), STAGES=2, PAIR=1, occ 2.
    constexpr int SMEM2 = 2 * (192 * 128 + 128 * 128) + 192 * 4;   // 82688

    auto* k1 = moe_gemm<0, 192, 256, 4, 2, 2, 11, 1>;
    auto* k2 = moe_gemm<1, 192, 128, 2, 2, 1, 11, 2>;
    cudaFuncSetAttribute(k1, cudaFuncAttributeMaxDynamicSharedMemorySize, SMEM1);
    cudaFuncSetAttribute(k2, cudaFuncAttributeMaxDynamicSharedMemorySize, SMEM2);

    // routing
    route_zero<<<(NEXP * CAP + 255) / 256, 256>>>(idxp, cntp);
    route_build<<<(T_TOK + 255) / 256, 256>>>(probs, idxp, slotp, cntp);

    // merged operand prep (W1^T, W2^T, X rounding overlap in one launch)
    prep<<<10240, 256>>>(w1, w1t, w2, w2t, x, xr);

    // routed GEMM1: gather X -> gelu*probs -> c1p.  grid (16, 44) x 256T
    k1<<<dim3(FFN / 256, NEXP * 11), 256, SMEM1>>>(
        xr, w1t, probs, idxp, cntp, c1p, HID);
    // routed GEMM2: c1p @ W2[e] -> y.               grid (8, 44) x 128T
    k2<<<dim3(HID / 128, NEXP * 11), 128, SMEM2>>>(
        c1p, w2t, probs, idxp, cntp, yp, FFN);
    // combine: out = resid + sum_topk y
    combine<<<T_TOK, 256>>>(yp, probs, slotp, resid, out);
}

// round 12
// speedup vs baseline: 1.3365x; 1.3365x over previous
#include <cuda_runtime.h>
#include <cstdint>

// ---------------------------------------------------------------------------
// MoE MLP, routed (top-k) formulation on legacy mma.sync tf32 HMMA
// (tcgen05 unavailable: harness compiles via non-'a' compute_103 PTX).
//
//   route:  per-expert compact token lists from probs>0 (TOPK=2 of E=4)
//   GEMM1:  a_e = gelu( X[list_e] @ W1[e] ) * probs[list_e,e]   (tf32-rounded)
//   GEMM2:  y_e = a_e @ W2[e]
//   combine: out[t] = resid[t] + sum_{e in topk(t)} y_e[slot(t,e)]
//
// R12: series-wide evidence says these GEMMs are latency-bound and
// warps-per-SMSP dominates (occ1 big tiles: 40-47% tensor; occ3 small
// tiles: best per-GEMM time). Both GEMMs now use CTA 96x128, 2x2 warps of
// 48x64 (96 acc regs -> fits 170-reg occ-3 budget), 2-stage, occupancy 3
// (12 warps/SM). Merged prep kept.
// ---------------------------------------------------------------------------

static constexpr int T_TOK = 2048;   // S*B
static constexpr int HID   = 1024;   // H
static constexpr int FFN   = 4096;   // F
static constexpr int NEXP  = 4;      // E
static constexpr int EF    = NEXP * FFN;  // 16384

static constexpr int CAP  = 2112;    // per-expert row capacity (96*22)

// static device scratch (no allocation allowed)
__device__ float g_xr  [(size_t)T_TOK * HID];      //   8 MB rounded X
__device__ float g_w1t [(size_t)EF * HID];         //  67 MB W1^T [e*F+f][h]
__device__ float g_w2t [(size_t)HID * EF];         //  67 MB W2^T [h][e*F+f]
__device__ float g_c1p [(size_t)NEXP * CAP * FFN]; // 138 MB compact act
__device__ float g_y   [(size_t)NEXP * CAP * HID]; //  35 MB compact y
__device__ int   g_idx [NEXP * CAP];               // expert -> token list
__device__ int   g_slot[T_TOK * NEXP];             // (t,e) -> slot
__device__ int   g_cnt [NEXP];

// ---------------------------------------------------------------------------
// helpers
// ---------------------------------------------------------------------------
__device__ __forceinline__ uint32_t smem_u32(const void* p) {
    uint32_t a;
    asm("{ .reg .u64 t; cvta.to.shared.u64 t, %1; cvt.u32.u64 %0, t; }"
        : "=r"(a) : "l"(p));
    return a;
}

__device__ __forceinline__ float to_tf32(float x) {
    uint32_t u;
    asm("cvt.rna.tf32.f32 %0, %1;" : "=r"(u) : "f"(x));
    return __uint_as_float(u);
}

__device__ __forceinline__ uint32_t sw128(uint32_t off) {
    return off ^ ((off >> 3) & 0x70);
}

__device__ __forceinline__ void cpa16(uint32_t dst, const void* src) {
    asm volatile("cp.async.cg.shared.global [%0], [%1], 16;"
                 :: "r"(dst), "l"(src) : "memory");
}

__device__ __forceinline__ void ldsm4(uint32_t* d, uint32_t addr) {
    asm volatile("ldmatrix.sync.aligned.m8n8.x4.shared.b16 {%0,%1,%2,%3}, [%4];"
                 : "=r"(d[0]), "=r"(d[1]), "=r"(d[2]), "=r"(d[3]) : "r"(addr));
}

__device__ __forceinline__ void mma8(float* c, const uint32_t* a,
                                     uint32_t b0, uint32_t b1) {
    asm volatile(
        "mma.sync.aligned.m16n8k8.row.col.f32.tf32.tf32.f32 "
        "{%0,%1,%2,%3}, {%4,%5,%6,%7}, {%8,%9}, {%0,%1,%2,%3};"
        : "+f"(c[0]), "+f"(c[1]), "+f"(c[2]), "+f"(c[3])
        : "r"(a[0]), "r"(a[1]), "r"(a[2]), "r"(a[3]), "r"(b0), "r"(b1));
}

__device__ __forceinline__ float gelu_exact(float x) {
    return 0.5f * x * (1.0f + erff(x * 0.70710678118654752f));
}

// ---------------------------------------------------------------------------
// merged operand prep: one launch, three independent DRAM-bound jobs overlap.
//   blocks [0, 4096):        W1 [E,H,F] -> w1t [E*F][H]   (transpose + round)
//   blocks [4096, 8192):     W2 [EF,H]  -> w2t [H][EF]    (transpose + round)
//   blocks [8192, 10240):    X round to tf32 grid
// ---------------------------------------------------------------------------
__device__ __forceinline__ void tr_tile(const float* __restrict__ in,
                                        float* __restrict__ out,
                                        int R, int C, int bx, int by, int bz,
                                        float (*tile)[68], int tid) {
    size_t base = (size_t)bz * R * C;
    int c0 = bx << 6, r0 = by << 6;
    int tx = tid & 15, ty = tid >> 4;              // 16 x 16
    #pragma unroll
    for (int i = 0; i < 4; i++) {
        int rr = ty + (i << 4);
        float4 v = *(const float4*)&in[base + (size_t)(r0 + rr) * C + c0 + (tx << 2)];
        tile[(tx << 2) + 0][rr] = to_tf32(v.x);
        tile[(tx << 2) + 1][rr] = to_tf32(v.y);
        tile[(tx << 2) + 2][rr] = to_tf32(v.z);
        tile[(tx << 2) + 3][rr] = to_tf32(v.w);
    }
    __syncthreads();
    #pragma unroll
    for (int i = 0; i < 4; i++) {
        int cc = ty + (i << 4);
        float4 w = *(const float4*)&tile[cc][tx << 2];
        *(float4*)&out[base + (size_t)(c0 + cc) * R + r0 + (tx << 2)] = w;
    }
}

__global__ void prep(const float* __restrict__ w1, float* __restrict__ w1t,
                     const float* __restrict__ w2, float* __restrict__ w2t,
                     const float* __restrict__ x,  float* __restrict__ xr) {
    __shared__ float tile[64][68];
    const int b   = blockIdx.x;
    const int tid = threadIdx.x;
    if (b < 4096) {                               // W1 transpose (per expert)
        int e   = b >> 10;                        // 1024 blocks / expert
        int rem = b & 1023;
        tr_tile(w1, w1t, HID, FFN, rem & 63, rem >> 6, e, tile, tid);
    } else if (b < 8192) {                        // W2 transpose
        int rem = b - 4096;                       // bx in [0,16), by in [0,256)
        tr_tile(w2, w2t, EF, HID, rem & 15, rem >> 4, 0, tile, tid);
    } else {                                      // X rounding
        int i = (b - 8192) * 256 + tid;           // float4 index
        float4 v = ((const float4*)x)[i];
        v.x = to_tf32(v.x); v.y = to_tf32(v.y);
        v.z = to_tf32(v.z); v.w = to_tf32(v.w);
        ((float4*)xr)[i] = v;
    }
}

// ---------------------------------------------------------------------------
// routing (zero every launch: graph replay must be stateless)
// ---------------------------------------------------------------------------
__global__ void route_zero(int* idx, int* cnt) {
    int i = blockIdx.x * 256 + threadIdx.x;
    if (i < NEXP * CAP) idx[i] = 0;
    if (i < NEXP) cnt[i] = 0;
}

__global__ void route_build(const float* __restrict__ probs,
                            int* idx, int* slot, int* cnt) {
    int t = blockIdx.x * 256 + threadIdx.x;
    if (t >= T_TOK) return;
    #pragma unroll
    for (int e = 0; e < NEXP; e++) {
        if (probs[t * NEXP + e] > 0.0f) {
            int pos = atomicAdd(&cnt[e], 1);
            idx[e * CAP + pos] = t;
            slot[t * NEXP + e] = pos;
        }
    }
}

// combine: out[t] = resid[t] + sum_e (probs>0) y[e][slot]
__global__ void combine(const float* __restrict__ y,
                        const float* __restrict__ probs,
                        const int* __restrict__ slot,
                        const float* __restrict__ resid,
                        float* __restrict__ out) {
    int t = blockIdx.x;
    int j = threadIdx.x;                          // 256 -> float4 over HID
    float4 acc = ((const float4*)resid)[t * (HID / 4) + j];
    #pragma unroll
    for (int e = 0; e < NEXP; e++) {
        if (probs[t * NEXP + e] > 0.0f) {
            int s = slot[t * NEXP + e];
            float4 v = ((const float4*)y)[((size_t)e * CAP + s) * (HID / 4) + j];
            acc.x += v.x; acc.y += v.y; acc.z += v.z; acc.w += v.w;
        }
    }
    ((float4*)out)[t * (HID / 4) + j] = acc;
}

// ---------------------------------------------------------------------------
// Routed GEMM. CTA tile 96x128, warp grid 2x2 (warp tile 48x64), BK=32,
// 2-stage cp.async pipeline, occupancy 3 (12 warps/SM: latency hiding via
// cross-CTA overlap — the empirically dominant factor in this series).
// grid (nb, e*TPE + mtile): blockIdx.x = n-block fastest (A-panel L2 reuse).
// CTAs past cnt[e] exit.
// MODE 0 (fc1): A rows gathered via token list; epi gelu*probs -> c1p (tf32).
// MODE 1 (fc2): A compact c1p rows; epi plain store -> y.
// ---------------------------------------------------------------------------
template<int MODE, int TPE>
__global__ void __launch_bounds__(128, 3)
moe_gemm(const float* __restrict__ A,     // MODE0: g_xr [T,H]; MODE1: g_c1p
         const float* __restrict__ Bt,    // MODE0: g_w1t [EF][H]; MODE1: g_w2t [H][EF]
         const float* __restrict__ probs, // [T,E]
         const int* __restrict__ idx,
         const int* __restrict__ cnt,
         float* __restrict__ Cout,        // MODE0: g_c1p; MODE1: g_y
         int K)                           // MODE0: HID; MODE1: FFN
{
    constexpr int BMT     = 96;
    constexpr int BNT     = 128;
    constexpr int THREADS = 128;
    constexpr int WM      = 48;           // warp tile M
    constexpr int MT      = 3;
    constexpr int NT      = 8;            // warp tile N = 64
    constexpr int A_BYTES = BMT * 128;    // 12288
    constexpr int B_BYTES = BNT * 128;    // 16384
    constexpr int STAGE   = A_BYTES + B_BYTES;

    extern __shared__ __align__(128) char smem[];
    const uint32_t sb = smem_u32(smem);
    int* s_token = (int*)(smem + 2 * STAGE);

    const int e    = blockIdx.y / TPE;
    const int tile = blockIdx.y % TPE;
    if (tile * BMT >= cnt[e]) return;

    const int tid  = threadIdx.x;
    const int wid  = tid >> 5;
    const int lane = tid & 31;
    const int wm   = wid >> 1;            // 0..1
    const int wn   = wid & 1;             // 0..1
    const int n0   = blockIdx.x * BNT;
    const int row_base = e * CAP + tile * BMT;

    if (MODE == 0) {
        for (int i = tid; i < BMT; i += THREADS) s_token[i] = idx[row_base + i];
    }
    __syncthreads();

    const int CCH = K / 32;

    auto issue = [&](int c, int s) {
        uint32_t dA = sb + (uint32_t)s * STAGE;
        uint32_t dB = dA + A_BYTES;
        const int k0 = c * 32;
        #pragma unroll
        for (int i = 0; i < BMT * 8 / THREADS; i++) {   // A: 96 rows x 2 x 16B
            int id2 = tid + i * THREADS;
            int row = id2 >> 3, cb = (id2 & 7) << 4;
            const float* asrc;
            if (MODE == 0)
                asrc = A + (size_t)s_token[row] * K + k0 + (cb >> 2);
            else
                asrc = A + (size_t)(row_base + row) * K + k0 + (cb >> 2);
            cpa16(dA + sw128((uint32_t)(row * 128 + cb)), asrc);
        }
        #pragma unroll
        for (int i = 0; i < BNT * 8 / THREADS; i++) {   // B: 128 rows K-contig
            int id2 = tid + i * THREADS;
            int row = id2 >> 3, cb = (id2 & 7) << 4;
            const float* bsrc;
            if (MODE == 0)   // w1t rows e*F + n, stride K (=HID)
                bsrc = Bt + (size_t)(e * FFN + n0 + row) * K + k0 + (cb >> 2);
            else             // w2t rows n (stride EF), expert cols e*F + k
                bsrc = Bt + (size_t)(n0 + row) * EF + e * FFN + k0 + (cb >> 2);
            cpa16(dB + sw128((uint32_t)(row * 128 + cb)), bsrc);
        }
    };

    issue(0, 0);
    asm volatile("cp.async.commit_group;" ::: "memory");

    float acc[MT][NT][4];
    #pragma unroll
    for (int mt = 0; mt < MT; mt++)
        #pragma unroll
        for (int nt = 0; nt < NT; nt++)
            #pragma unroll
            for (int i = 0; i < 4; i++) acc[mt][nt][i] = 0.0f;

    const int g = lane >> 3, r = lane & 7;

    #pragma unroll 1
    for (int c = 0; c < CCH; c++) {
        asm volatile("cp.async.wait_group 0;" ::: "memory");
        __syncthreads();
        if (c + 1 < CCH) issue(c + 1, (c + 1) & 1);
        asm volatile("cp.async.commit_group;" ::: "memory");

        const uint32_t sA  = sb + (uint32_t)(c & 1) * STAGE;
        const uint32_t sBm = sA + A_BYTES;

        #pragma unroll
        for (int ks = 0; ks < 4; ks++) {
            uint32_t bf[NT * 2];
            #pragma unroll
            for (int p = 0; p < NT / 2; p++) {
                int brow = wn * 64 + p * 16 + ((g >> 1) << 3) + r;
                int bcol = ks * 32 + ((g & 1) << 4);
                ldsm4(&bf[4 * p], sBm + sw128((uint32_t)(brow * 128 + bcol)));
            }
            uint32_t af[2][4];
            {
                int arow = wm * WM + ((g & 1) << 3) + r;
                int acol = ks * 32 + ((g >> 1) << 4);
                ldsm4(af[0], sA + sw128((uint32_t)(arow * 128 + acol)));
            }
            #pragma unroll
            for (int mt = 0; mt < MT; mt++) {
                if (mt + 1 < MT) {
                    int arow = wm * WM + (mt + 1) * 16 + ((g & 1) << 3) + r;
                    int acol = ks * 32 + ((g >> 1) << 4);
                    ldsm4(af[(mt + 1) & 1], sA + sw128((uint32_t)(arow * 128 + acol)));
                }
                #pragma unroll
                for (int nt = 0; nt < NT; nt++)
                    mma8(acc[mt][nt], af[mt & 1], bf[nt * 2], bf[nt * 2 + 1]);
            }
        }
    }

    // ---------------- epilogue ----------------
    const int qr = lane >> 2, rm = lane & 3;
    const int ldc = (MODE == 0) ? FFN : HID;

    #pragma unroll
    for (int mt = 0; mt < MT; mt++) {
        const int lr0 = wm * WM + mt * 16 + qr;
        const int lr1 = lr0 + 8;
        float p0 = 1.0f, p1 = 1.0f;
        if (MODE == 0) {
            p0 = probs[s_token[lr0] * NEXP + e];
            p1 = probs[s_token[lr1] * NEXP + e];
        }
        #pragma unroll
        for (int nt = 0; nt < NT; nt++) {
            const int col = n0 + wn * 64 + nt * 8 + (rm << 1);
            float2 v0, v1;
            if (MODE == 0) {
                v0.x = to_tf32(gelu_exact(acc[mt][nt][0]) * p0);
                v0.y = to_tf32(gelu_exact(acc[mt][nt][1]) * p0);
                v1.x = to_tf32(gelu_exact(acc[mt][nt][2]) * p1);
                v1.y = to_tf32(gelu_exact(acc[mt][nt][3]) * p1);
            } else {
                v0.x = acc[mt][nt][0]; v0.y = acc[mt][nt][1];
                v1.x = acc[mt][nt][2]; v1.y = acc[mt][nt][3];
            }
            *(float2*)&Cout[(size_t)(row_base + lr0) * ldc + col] = v0;
            *(float2*)&Cout[(size_t)(row_base + lr1) * ldc + col] = v1;
        }
    }
}

// ---------------------------------------------------------------------------
// launch
// ---------------------------------------------------------------------------
extern "C" void kernel_launch(void* const* d_in, const int* in_sizes, int n_in,
                              void* d_out, int out_size) {
    const float* x     = (const float*)d_in[0];   // hidden_states [T,H]
    const float* resid = (const float*)d_in[1];   // mlp_residual  [T,H]
    const float* probs = (const float*)d_in[2];   // probs [T,E] (masked)
    // d_in[3] = routing_map (unused: probs>0 is the same mask, dtype-safe)
    const float* w1    = (const float*)d_in[4];   // [E,H,F]
    const float* w2    = (const float*)d_in[5];   // [E,F,H]
    float* out = (float*)d_out;

    float *xr, *w1t, *w2t, *c1p, *yp;
    int *idxp, *slotp, *cntp;
    cudaGetSymbolAddress((void**)&xr,   g_xr);
    cudaGetSymbolAddress((void**)&w1t,  g_w1t);
    cudaGetSymbolAddress((void**)&w2t,  g_w2t);
    cudaGetSymbolAddress((void**)&c1p,  g_c1p);
    cudaGetSymbolAddress((void**)&yp,   g_y);
    cudaGetSymbolAddress((void**)&idxp, g_idx);
    cudaGetSymbolAddress((void**)&slotp, g_slot);
    cudaGetSymbolAddress((void**)&cntp, g_cnt);

    // both GEMMs: 96x128 CTA, 2-stage, occ 3.  smem = 2*28672 + 384 = 57728
    constexpr int SMEM = 2 * (96 * 128 + 128 * 128) + 96 * 4;
    auto* k1 = moe_gemm<0, 22>;
    auto* k2 = moe_gemm<1, 22>;
    cudaFuncSetAttribute(k1, cudaFuncAttributeMaxDynamicSharedMemorySize, SMEM);
    cudaFuncSetAttribute(k2, cudaFuncAttributeMaxDynamicSharedMemorySize, SMEM);

    // routing
    route_zero<<<(NEXP * CAP + 255) / 256, 256>>>(idxp, cntp);
    route_build<<<(T_TOK + 255) / 256, 256>>>(probs, idxp, slotp, cntp);

    // merged operand prep (W1^T, W2^T, X rounding overlap in one launch)
    prep<<<10240, 256>>>(w1, w1t, w2, w2t, x, xr);

    // routed GEMM1: gather X -> gelu*probs -> c1p.  grid (32, 88) x 128T
    k1<<<dim3(FFN / 128, NEXP * 22), 128, SMEM>>>(
        xr, w1t, probs, idxp, cntp, c1p, HID);
    // routed GEMM2: c1p @ W2[e] -> y.               grid (8, 88) x 128T
    k2<<<dim3(HID / 128, NEXP * 22), 128, SMEM>>>(
        c1p, w2t, probs, idxp, cntp, yp, FFN);
    // combine: out = resid + sum_topk y
    combine<<<T_TOK, 256>>>(yp, probs, slotp, resid, out);
}

// round 13
// speedup vs baseline: 1.3895x; 1.0396x over previous
#include <cuda_runtime.h>
#include <cstdint>

// ---------------------------------------------------------------------------
// MoE MLP, routed (top-k) formulation on legacy mma.sync tf32 HMMA
// (tcgen05 unavailable: harness compiles via non-'a' compute_103 PTX).
//
//   route:  per-expert compact token lists from probs>0 (TOPK=2 of E=4)
//   GEMM1:  a_e = gelu( X[list_e] @ W1[e] ) * probs[list_e,e]   (tf32-rounded)
//   GEMM2:  y_e = a_e @ W2[e]
//   combine: out[t] = resid[t] + sum_{e in topk(t)} y_e[slot(t,e)]
//
// R13: R12 confirmed occupancy-3 dominates. Now add pipeline depth WITHOUT
// losing occ 3: CTA 64x128 (warp 32x64, 2x2), 3-stage cp.async (stage 24KB,
// 3x = 72KB -> still 3 CTAs/SM), single barrier per chunk (wait_group 1,
// always-commit). Prefetch distance 1 -> 2 chunks. Routing kernels merged.
// ---------------------------------------------------------------------------

static constexpr int T_TOK = 2048;   // S*B
static constexpr int HID   = 1024;   // H
static constexpr int FFN   = 4096;   // F
static constexpr int NEXP  = 4;      // E
static constexpr int EF    = NEXP * FFN;  // 16384

static constexpr int CAP  = 2112;    // per-expert row capacity (64*33)
static constexpr int TPE  = 33;      // m-tiles per expert (CAP/64)

// static device scratch (no allocation allowed)
__device__ float g_xr  [(size_t)T_TOK * HID];      //   8 MB rounded X
__device__ float g_w1t [(size_t)EF * HID];         //  67 MB W1^T [e*F+f][h]
__device__ float g_w2t [(size_t)HID * EF];         //  67 MB W2^T [h][e*F+f]
__device__ float g_c1p [(size_t)NEXP * CAP * FFN]; // 138 MB compact act
__device__ float g_y   [(size_t)NEXP * CAP * HID]; //  35 MB compact y
__device__ int   g_idx [NEXP * CAP];               // expert -> token list
__device__ int   g_slot[T_TOK * NEXP];             // (t,e) -> slot
__device__ int   g_cnt [NEXP];

// ---------------------------------------------------------------------------
// helpers
// ---------------------------------------------------------------------------
__device__ __forceinline__ uint32_t smem_u32(const void* p) {
    uint32_t a;
    asm("{ .reg .u64 t; cvta.to.shared.u64 t, %1; cvt.u32.u64 %0, t; }"
        : "=r"(a) : "l"(p));
    return a;
}

__device__ __forceinline__ float to_tf32(float x) {
    uint32_t u;
    asm("cvt.rna.tf32.f32 %0, %1;" : "=r"(u) : "f"(x));
    return __uint_as_float(u);
}

__device__ __forceinline__ uint32_t sw128(uint32_t off) {
    return off ^ ((off >> 3) & 0x70);
}

__device__ __forceinline__ void cpa16(uint32_t dst, const void* src) {
    asm volatile("cp.async.cg.shared.global [%0], [%1], 16;"
                 :: "r"(dst), "l"(src) : "memory");
}

__device__ __forceinline__ void ldsm4(uint32_t* d, uint32_t addr) {
    asm volatile("ldmatrix.sync.aligned.m8n8.x4.shared.b16 {%0,%1,%2,%3}, [%4];"
                 : "=r"(d[0]), "=r"(d[1]), "=r"(d[2]), "=r"(d[3]) : "r"(addr));
}

__device__ __forceinline__ void mma8(float* c, const uint32_t* a,
                                     uint32_t b0, uint32_t b1) {
    asm volatile(
        "mma.sync.aligned.m16n8k8.row.col.f32.tf32.tf32.f32 "
        "{%0,%1,%2,%3}, {%4,%5,%6,%7}, {%8,%9}, {%0,%1,%2,%3};"
        : "+f"(c[0]), "+f"(c[1]), "+f"(c[2]), "+f"(c[3])
        : "r"(a[0]), "r"(a[1]), "r"(a[2]), "r"(a[3]), "r"(b0), "r"(b1));
}

__device__ __forceinline__ float gelu_exact(float x) {
    return 0.5f * x * (1.0f + erff(x * 0.70710678118654752f));
}

// ---------------------------------------------------------------------------
// merged operand prep: one launch, three independent DRAM-bound jobs overlap.
//   blocks [0, 4096):        W1 [E,H,F] -> w1t [E*F][H]   (transpose + round)
//   blocks [4096, 8192):     W2 [EF,H]  -> w2t [H][EF]    (transpose + round)
//   blocks [8192, 10240):    X round to tf32 grid
// ---------------------------------------------------------------------------
__device__ __forceinline__ void tr_tile(const float* __restrict__ in,
                                        float* __restrict__ out,
                                        int R, int C, int bx, int by, int bz,
                                        float (*tile)[68], int tid) {
    size_t base = (size_t)bz * R * C;
    int c0 = bx << 6, r0 = by << 6;
    int tx = tid & 15, ty = tid >> 4;              // 16 x 16
    #pragma unroll
    for (int i = 0; i < 4; i++) {
        int rr = ty + (i << 4);
        float4 v = *(const float4*)&in[base + (size_t)(r0 + rr) * C + c0 + (tx << 2)];
        tile[(tx << 2) + 0][rr] = to_tf32(v.x);
        tile[(tx << 2) + 1][rr] = to_tf32(v.y);
        tile[(tx << 2) + 2][rr] = to_tf32(v.z);
        tile[(tx << 2) + 3][rr] = to_tf32(v.w);
    }
    __syncthreads();
    #pragma unroll
    for (int i = 0; i < 4; i++) {
        int cc = ty + (i << 4);
        float4 w = *(const float4*)&tile[cc][tx << 2];
        *(float4*)&out[base + (size_t)(c0 + cc) * R + r0 + (tx << 2)] = w;
    }
}

__global__ void prep(const float* __restrict__ w1, float* __restrict__ w1t,
                     const float* __restrict__ w2, float* __restrict__ w2t,
                     const float* __restrict__ x,  float* __restrict__ xr) {
    __shared__ float tile[64][68];
    const int b   = blockIdx.x;
    const int tid = threadIdx.x;
    if (b < 4096) {                               // W1 transpose (per expert)
        int e   = b >> 10;                        // 1024 blocks / expert
        int rem = b & 1023;
        tr_tile(w1, w1t, HID, FFN, rem & 63, rem >> 6, e, tile, tid);
    } else if (b < 8192) {                        // W2 transpose
        int rem = b - 4096;                       // bx in [0,16), by in [0,256)
        tr_tile(w2, w2t, EF, HID, rem & 15, rem >> 4, 0, tile, tid);
    } else {                                      // X rounding
        int i = (b - 8192) * 256 + tid;           // float4 index
        float4 v = ((const float4*)x)[i];
        v.x = to_tf32(v.x); v.y = to_tf32(v.y);
        v.z = to_tf32(v.z); v.w = to_tf32(v.w);
        ((float4*)xr)[i] = v;
    }
}

// ---------------------------------------------------------------------------
// routing: zero + build in one kernel (grid-sized for the zero pass; the
// build pass runs in the first T_TOK threads after a device-wide dependency
// is unnecessary — zero and build touch disjoint elements per thread except
// idx, which build writes only at positions < cnt; we zero idx here and
// build in a SECOND kernel to keep the atomics ordered after zeroing).
// ---------------------------------------------------------------------------
__global__ void route_zero(int* idx, int* cnt) {
    int i = blockIdx.x * 256 + threadIdx.x;
    if (i < NEXP * CAP) idx[i] = 0;
    if (i < NEXP) cnt[i] = 0;
}

__global__ void route_build(const float* __restrict__ probs,
                            int* idx, int* slot, int* cnt) {
    int t = blockIdx.x * 256 + threadIdx.x;
    if (t >= T_TOK) return;
    #pragma unroll
    for (int e = 0; e < NEXP; e++) {
        if (probs[t * NEXP + e] > 0.0f) {
            int pos = atomicAdd(&cnt[e], 1);
            idx[e * CAP + pos] = t;
            slot[t * NEXP + e] = pos;
        }
    }
}

// combine: out[t] = resid[t] + sum_e (probs>0) y[e][slot]
__global__ void combine(const float* __restrict__ y,
                        const float* __restrict__ probs,
                        const int* __restrict__ slot,
                        const float* __restrict__ resid,
                        float* __restrict__ out) {
    int t = blockIdx.x;
    int j = threadIdx.x;                          // 256 -> float4 over HID
    float4 acc = ((const float4*)resid)[t * (HID / 4) + j];
    #pragma unroll
    for (int e = 0; e < NEXP; e++) {
        if (probs[t * NEXP + e] > 0.0f) {
            int s = slot[t * NEXP + e];
            float4 v = ((const float4*)y)[((size_t)e * CAP + s) * (HID / 4) + j];
            acc.x += v.x; acc.y += v.y; acc.z += v.z; acc.w += v.w;
        }
    }
    ((float4*)out)[t * (HID / 4) + j] = acc;
}

// ---------------------------------------------------------------------------
// Routed GEMM. CTA tile 64x128, warp grid 2x2 (warp tile 32x64), BK=32,
// 3-stage cp.async pipeline (prefetch distance 2), ONE barrier per chunk
// (wait_group 1, always-commit), occupancy 3 (12 warps/SM).
// grid (nb, e*TPE + mtile): blockIdx.x = n-block fastest (A-panel L2 reuse).
// CTAs past cnt[e] exit.
// MODE 0 (fc1): A rows gathered via token list; epi gelu*probs -> c1p (tf32).
// MODE 1 (fc2): A compact c1p rows; epi plain store -> y.
// ---------------------------------------------------------------------------
template<int MODE>
__global__ void __launch_bounds__(128, 3)
moe_gemm(const float* __restrict__ A,     // MODE0: g_xr [T,H]; MODE1: g_c1p
         const float* __restrict__ Bt,    // MODE0: g_w1t [EF][H]; MODE1: g_w2t [H][EF]
         const float* __restrict__ probs, // [T,E]
         const int* __restrict__ idx,
         const int* __restrict__ cnt,
         float* __restrict__ Cout,        // MODE0: g_c1p; MODE1: g_y
         int K)                           // MODE0: HID; MODE1: FFN
{
    constexpr int BMT     = 64;
    constexpr int BNT     = 128;
    constexpr int THREADS = 128;
    constexpr int STAGES  = 3;
    constexpr int WM      = 32;           // warp tile M
    constexpr int MT      = 2;
    constexpr int NT      = 8;            // warp tile N = 64
    constexpr int A_BYTES = BMT * 128;    // 8192
    constexpr int B_BYTES = BNT * 128;    // 16384
    constexpr int STAGE   = A_BYTES + B_BYTES;   // 24576

    extern __shared__ __align__(128) char smem[];
    const uint32_t sb = smem_u32(smem);
    int* s_token = (int*)(smem + STAGES * STAGE);

    const int e    = blockIdx.y / TPE;
    const int tile = blockIdx.y % TPE;
    if (tile * BMT >= cnt[e]) return;

    const int tid  = threadIdx.x;
    const int wid  = tid >> 5;
    const int lane = tid & 31;
    const int wm   = wid >> 1;            // 0..1
    const int wn   = wid & 1;             // 0..1
    const int n0   = blockIdx.x * BNT;
    const int row_base = e * CAP + tile * BMT;

    if (MODE == 0) {
        if (tid < BMT) s_token[tid] = idx[row_base + tid];
    }
    __syncthreads();

    const int CCH = K / 32;

    auto issue = [&](int c, int s) {
        uint32_t dA = sb + (uint32_t)s * STAGE;
        uint32_t dB = dA + A_BYTES;
        const int k0 = c * 32;
        #pragma unroll
        for (int i = 0; i < BMT * 8 / THREADS; i++) {   // A: 64 rows x 2 x 16B
            int id2 = tid + i * THREADS;
            int row = id2 >> 3, cb = (id2 & 7) << 4;
            const float* asrc;
            if (MODE == 0)
                asrc = A + (size_t)s_token[row] * K + k0 + (cb >> 2);
            else
                asrc = A + (size_t)(row_base + row) * K + k0 + (cb >> 2);
            cpa16(dA + sw128((uint32_t)(row * 128 + cb)), asrc);
        }
        #pragma unroll
        for (int i = 0; i < BNT * 8 / THREADS; i++) {   // B: 128 rows K-contig
            int id2 = tid + i * THREADS;
            int row = id2 >> 3, cb = (id2 & 7) << 4;
            const float* bsrc;
            if (MODE == 0)   // w1t rows e*F + n, stride K (=HID)
                bsrc = Bt + (size_t)(e * FFN + n0 + row) * K + k0 + (cb >> 2);
            else             // w2t rows n (stride EF), expert cols e*F + k
                bsrc = Bt + (size_t)(n0 + row) * EF + e * FFN + k0 + (cb >> 2);
            cpa16(dB + sw128((uint32_t)(row * 128 + cb)), bsrc);
        }
    };

    // prologue: stages 0,1
    #pragma unroll
    for (int s = 0; s < STAGES - 1; s++) {
        issue(s, s);
        asm volatile("cp.async.commit_group;" ::: "memory");
    }

    float acc[MT][NT][4];
    #pragma unroll
    for (int mt = 0; mt < MT; mt++)
        #pragma unroll
        for (int nt = 0; nt < NT; nt++)
            #pragma unroll
            for (int i = 0; i < 4; i++) acc[mt][nt][i] = 0.0f;

    const int g = lane >> 3, r = lane & 7;

    #pragma unroll 1
    for (int c = 0; c < CCH; c++) {
        // commits so far = 2 + c; allow 1 pending -> chunk c resident
        asm volatile("cp.async.wait_group 1;" ::: "memory");
        __syncthreads();
        // buffer (c+2)%3 == (c-1)%3: its readers finished before the barrier
        if (c + STAGES - 1 < CCH) issue(c + STAGES - 1, (c + STAGES - 1) % STAGES);
        asm volatile("cp.async.commit_group;" ::: "memory");  // uniform count

        const uint32_t sA  = sb + (uint32_t)(c % STAGES) * STAGE;
        const uint32_t sBm = sA + A_BYTES;

        #pragma unroll
        for (int ks = 0; ks < 4; ks++) {
            uint32_t bf[NT * 2];
            #pragma unroll
            for (int p = 0; p < NT / 2; p++) {
                int brow = wn * 64 + p * 16 + ((g >> 1) << 3) + r;
                int bcol = ks * 32 + ((g & 1) << 4);
                ldsm4(&bf[4 * p], sBm + sw128((uint32_t)(brow * 128 + bcol)));
            }
            uint32_t af[2][4];
            {
                int arow = wm * WM + ((g & 1) << 3) + r;
                int acol = ks * 32 + ((g >> 1) << 4);
                ldsm4(af[0], sA + sw128((uint32_t)(arow * 128 + acol)));
            }
            #pragma unroll
            for (int mt = 0; mt < MT; mt++) {
                if (mt + 1 < MT) {
                    int arow = wm * WM + (mt + 1) * 16 + ((g & 1) << 3) + r;
                    int acol = ks * 32 + ((g >> 1) << 4);
                    ldsm4(af[(mt + 1) & 1], sA + sw128((uint32_t)(arow * 128 + acol)));
                }
                #pragma unroll
                for (int nt = 0; nt < NT; nt++)
                    mma8(acc[mt][nt], af[mt & 1], bf[nt * 2], bf[nt * 2 + 1]);
            }
        }
    }

    // ---------------- epilogue ----------------
    const int qr = lane >> 2, rm = lane & 3;
    const int ldc = (MODE == 0) ? FFN : HID;

    #pragma unroll
    for (int mt = 0; mt < MT; mt++) {
        const int lr0 = wm * WM + mt * 16 + qr;
        const int lr1 = lr0 + 8;
        float p0 = 1.0f, p1 = 1.0f;
        if (MODE == 0) {
            p0 = probs[s_token[lr0] * NEXP + e];
            p1 = probs[s_token[lr1] * NEXP + e];
        }
        #pragma unroll
        for (int nt = 0; nt < NT; nt++) {
            const int col = n0 + wn * 64 + nt * 8 + (rm << 1);
            float2 v0, v1;
            if (MODE == 0) {
                v0.x = to_tf32(gelu_exact(acc[mt][nt][0]) * p0);
                v0.y = to_tf32(gelu_exact(acc[mt][nt][1]) * p0);
                v1.x = to_tf32(gelu_exact(acc[mt][nt][2]) * p1);
                v1.y = to_tf32(gelu_exact(acc[mt][nt][3]) * p1);
            } else {
                v0.x = acc[mt][nt][0]; v0.y = acc[mt][nt][1];
                v1.x = acc[mt][nt][2]; v1.y = acc[mt][nt][3];
            }
            *(float2*)&Cout[(size_t)(row_base + lr0) * ldc + col] = v0;
            *(float2*)&Cout[(size_t)(row_base + lr1) * ldc + col] = v1;
        }
    }
}

// ---------------------------------------------------------------------------
// launch
// ---------------------------------------------------------------------------
extern "C" void kernel_launch(void* const* d_in, const int* in_sizes, int n_in,
                              void* d_out, int out_size) {
    const float* x     = (const float*)d_in[0];   // hidden_states [T,H]
    const float* resid = (const float*)d_in[1];   // mlp_residual  [T,H]
    const float* probs = (const float*)d_in[2];   // probs [T,E] (masked)
    // d_in[3] = routing_map (unused: probs>0 is the same mask, dtype-safe)
    const float* w1    = (const float*)d_in[4];   // [E,H,F]
    const float* w2    = (const float*)d_in[5];   // [E,F,H]
    float* out = (float*)d_out;

    float *xr, *w1t, *w2t, *c1p, *yp;
    int *idxp, *slotp, *cntp;
    cudaGetSymbolAddress((void**)&xr,   g_xr);
    cudaGetSymbolAddress((void**)&w1t,  g_w1t);
    cudaGetSymbolAddress((void**)&w2t,  g_w2t);
    cudaGetSymbolAddress((void**)&c1p,  g_c1p);
    cudaGetSymbolAddress((void**)&yp,   g_y);
    cudaGetSymbolAddress((void**)&idxp, g_idx);
    cudaGetSymbolAddress((void**)&slotp, g_slot);
    cudaGetSymbolAddress((void**)&cntp, g_cnt);

    // both GEMMs: 64x128 CTA, 3-stage, occ 3.
    // smem = 3*24576 + 256 = 73984; x3 CTAs = 221952 <= 228KB.
    constexpr int SMEM = 3 * (64 * 128 + 128 * 128) + 64 * 4;
    auto* k1 = moe_gemm<0>;
    auto* k2 = moe_gemm<1>;
    cudaFuncSetAttribute(k1, cudaFuncAttributeMaxDynamicSharedMemorySize, SMEM);
    cudaFuncSetAttribute(k2, cudaFuncAttributeMaxDynamicSharedMemorySize, SMEM);

    // routing
    route_zero<<<(NEXP * CAP + 255) / 256, 256>>>(idxp, cntp);
    route_build<<<(T_TOK + 255) / 256, 256>>>(probs, idxp, slotp, cntp);

    // merged operand prep (W1^T, W2^T, X rounding overlap in one launch)
    prep<<<10240, 256>>>(w1, w1t, w2, w2t, x, xr);

    // routed GEMM1: gather X -> gelu*probs -> c1p.  grid (32, 132) x 128T
    k1<<<dim3(FFN / 128, NEXP * TPE), 128, SMEM>>>(
        xr, w1t, probs, idxp, cntp, c1p, HID);
    // routed GEMM2: c1p @ W2[e] -> y.               grid (8, 132) x 128T
    k2<<<dim3(HID / 128, NEXP * TPE), 128, SMEM>>>(
        c1p, w2t, probs, idxp, cntp, yp, FFN);
    // combine: out = resid + sum_topk y
    combine<<<T_TOK, 256>>>(yp, probs, slotp, resid, out);
}

// round 14
// speedup vs baseline: 1.4061x; 1.0120x over previous
#include <cuda_runtime.h>
#include <cstdint>

// ---------------------------------------------------------------------------
// MoE MLP, routed (top-k) formulation on legacy mma.sync tf32 HMMA
// (tcgen05 unavailable: harness compiles via non-'a' compute_103 PTX).
//
//   route:  per-expert compact token lists from probs>0 (TOPK=2 of E=4)
//   GEMM1:  a_e = gelu( X[list_e] @ W1[e] ) * probs[list_e,e]   (tf32-rounded)
//   GEMM2:  y_e = a_e @ W2[e]
//   combine: out[t] = resid[t] + sum_{e in topk(t)} y_e[slot(t,e)]
//
// R14 (GEMM mainloop frozen at R13 optimum):
//   (a) route_zero eliminated: idx entries are always valid token ids
//       (static zero-init + prior route_build writes; padded rows only feed
//       c1p/y rows combine never reads). cnt zeroed at END of launch by
//       combine -> stateless replays.
//   (b) route_build merged into prep (one launch).
//   (c) k1 grid swapped to mtile-fastest so adjacent CTAs share the 16KB/chunk
//       B slab in L2 (w1t pulled ~1x instead of ~16x).
// ---------------------------------------------------------------------------

static constexpr int T_TOK = 2048;   // S*B
static constexpr int HID   = 1024;   // H
static constexpr int FFN   = 4096;   // F
static constexpr int NEXP  = 4;      // E
static constexpr int EF    = NEXP * FFN;  // 16384

static constexpr int CAP  = 2112;    // per-expert row capacity (64*33)
static constexpr int TPE  = 33;      // m-tiles per expert (CAP/64)

// static device scratch (no allocation allowed)
__device__ float g_xr  [(size_t)T_TOK * HID];      //   8 MB rounded X
__device__ float g_w1t [(size_t)EF * HID];         //  67 MB W1^T [e*F+f][h]
__device__ float g_w2t [(size_t)HID * EF];         //  67 MB W2^T [h][e*F+f]
__device__ float g_c1p [(size_t)NEXP * CAP * FFN]; // 138 MB compact act
__device__ float g_y   [(size_t)NEXP * CAP * HID]; //  35 MB compact y
__device__ int   g_idx [NEXP * CAP];               // expert -> token list (always valid ids)
__device__ int   g_slot[T_TOK * NEXP];             // (t,e) -> slot
__device__ int   g_cnt [NEXP];                     // zero at launch entry (see combine)

// ---------------------------------------------------------------------------
// helpers
// ---------------------------------------------------------------------------
__device__ __forceinline__ uint32_t smem_u32(const void* p) {
    uint32_t a;
    asm("{ .reg .u64 t; cvta.to.shared.u64 t, %1; cvt.u32.u64 %0, t; }"
        : "=r"(a) : "l"(p));
    return a;
}

__device__ __forceinline__ float to_tf32(float x) {
    uint32_t u;
    asm("cvt.rna.tf32.f32 %0, %1;" : "=r"(u) : "f"(x));
    return __uint_as_float(u);
}

__device__ __forceinline__ uint32_t sw128(uint32_t off) {
    return off ^ ((off >> 3) & 0x70);
}

__device__ __forceinline__ void cpa16(uint32_t dst, const void* src) {
    asm volatile("cp.async.cg.shared.global [%0], [%1], 16;"
                 :: "r"(dst), "l"(src) : "memory");
}

__device__ __forceinline__ void ldsm4(uint32_t* d, uint32_t addr) {
    asm volatile("ldmatrix.sync.aligned.m8n8.x4.shared.b16 {%0,%1,%2,%3}, [%4];"
                 : "=r"(d[0]), "=r"(d[1]), "=r"(d[2]), "=r"(d[3]) : "r"(addr));
}

__device__ __forceinline__ void mma8(float* c, const uint32_t* a,
                                     uint32_t b0, uint32_t b1) {
    asm volatile(
        "mma.sync.aligned.m16n8k8.row.col.f32.tf32.tf32.f32 "
        "{%0,%1,%2,%3}, {%4,%5,%6,%7}, {%8,%9}, {%0,%1,%2,%3};"
        : "+f"(c[0]), "+f"(c[1]), "+f"(c[2]), "+f"(c[3])
        : "r"(a[0]), "r"(a[1]), "r"(a[2]), "r"(a[3]), "r"(b0), "r"(b1));
}

__device__ __forceinline__ float gelu_exact(float x) {
    return 0.5f * x * (1.0f + erff(x * 0.70710678118654752f));
}

// ---------------------------------------------------------------------------
// merged operand prep + routing: one launch, independent jobs overlap.
//   blocks [0, 4096):      W1 [E,H,F] -> w1t [E*F][H]   (transpose + round)
//   blocks [4096, 8192):   W2 [EF,H]  -> w2t [H][EF]    (transpose + round)
//   blocks [8192, 10240):  X round to tf32 grid
//   blocks [10240, 10248): route_build (cnt is zero at launch entry)
// ---------------------------------------------------------------------------
__device__ __forceinline__ void tr_tile(const float* __restrict__ in,
                                        float* __restrict__ out,
                                        int R, int C, int bx, int by, int bz,
                                        float (*tile)[68], int tid) {
    size_t base = (size_t)bz * R * C;
    int c0 = bx << 6, r0 = by << 6;
    int tx = tid & 15, ty = tid >> 4;              // 16 x 16
    #pragma unroll
    for (int i = 0; i < 4; i++) {
        int rr = ty + (i << 4);
        float4 v = *(const float4*)&in[base + (size_t)(r0 + rr) * C + c0 + (tx << 2)];
        tile[(tx << 2) + 0][rr] = to_tf32(v.x);
        tile[(tx << 2) + 1][rr] = to_tf32(v.y);
        tile[(tx << 2) + 2][rr] = to_tf32(v.z);
        tile[(tx << 2) + 3][rr] = to_tf32(v.w);
    }
    __syncthreads();
    #pragma unroll
    for (int i = 0; i < 4; i++) {
        int cc = ty + (i << 4);
        float4 w = *(const float4*)&tile[cc][tx << 2];
        *(float4*)&out[base + (size_t)(c0 + cc) * R + r0 + (tx << 2)] = w;
    }
}

__global__ void prep(const float* __restrict__ w1, float* __restrict__ w1t,
                     const float* __restrict__ w2, float* __restrict__ w2t,
                     const float* __restrict__ x,  float* __restrict__ xr,
                     const float* __restrict__ probs,
                     int* idx, int* slot, int* cnt) {
    __shared__ float tile[64][68];
    const int b   = blockIdx.x;
    const int tid = threadIdx.x;
    if (b < 4096) {                               // W1 transpose (per expert)
        int e   = b >> 10;                        // 1024 blocks / expert
        int rem = b & 1023;
        tr_tile(w1, w1t, HID, FFN, rem & 63, rem >> 6, e, tile, tid);
    } else if (b < 8192) {                        // W2 transpose
        int rem = b - 4096;                       // bx in [0,16), by in [0,256)
        tr_tile(w2, w2t, EF, HID, rem & 15, rem >> 4, 0, tile, tid);
    } else if (b < 10240) {                       // X rounding
        int i = (b - 8192) * 256 + tid;           // float4 index
        float4 v = ((const float4*)x)[i];
        v.x = to_tf32(v.x); v.y = to_tf32(v.y);
        v.z = to_tf32(v.z); v.w = to_tf32(v.w);
        ((float4*)xr)[i] = v;
    } else {                                      // routing build
        int t = (b - 10240) * 256 + tid;
        if (t < T_TOK) {
            #pragma unroll
            for (int e = 0; e < NEXP; e++) {
                if (probs[t * NEXP + e] > 0.0f) {
                    int pos = atomicAdd(&cnt[e], 1);
                    idx[e * CAP + pos] = t;
                    slot[t * NEXP + e] = pos;
                }
            }
        }
    }
}

// combine: out[t] = resid[t] + sum_e (probs>0) y[e][slot];
// block 0 also resets cnt to 0 so the NEXT launch (graph replay) starts clean.
__global__ void combine(const float* __restrict__ y,
                        const float* __restrict__ probs,
                        const int* __restrict__ slot,
                        const float* __restrict__ resid,
                        float* __restrict__ out,
                        int* cnt) {
    int t = blockIdx.x;
    int j = threadIdx.x;                          // 256 -> float4 over HID
    if (t == 0 && j < NEXP) cnt[j] = 0;
    float4 acc = ((const float4*)resid)[t * (HID / 4) + j];
    #pragma unroll
    for (int e = 0; e < NEXP; e++) {
        if (probs[t * NEXP + e] > 0.0f) {
            int s = slot[t * NEXP + e];
            float4 v = ((const float4*)y)[((size_t)e * CAP + s) * (HID / 4) + j];
            acc.x += v.x; acc.y += v.y; acc.z += v.z; acc.w += v.w;
        }
    }
    ((float4*)out)[t * (HID / 4) + j] = acc;
}

// ---------------------------------------------------------------------------
// Routed GEMM (R13 mainloop, frozen). CTA tile 64x128, warp grid 2x2 (warp
// tile 32x64), BK=32, 3-stage cp.async (prefetch distance 2), ONE barrier per
// chunk (wait_group 1, always-commit), occupancy 3 (12 warps/SM).
// Grid mapping:
//   MODE 0: blockIdx.x = mtile (fastest -> adjacent CTAs share the B slab in
//           L2), blockIdx.y = e*32 + nb.
//   MODE 1: blockIdx.x = nb (fastest -> adjacent CTAs share the c1p A panel),
//           blockIdx.y = e*TPE + mtile.
// CTAs past cnt[e] exit. idx entries are always valid token ids (see header).
// MODE 0 (fc1): A rows gathered via token list; epi gelu*probs -> c1p (tf32).
// MODE 1 (fc2): A compact c1p rows; epi plain store -> y.
// ---------------------------------------------------------------------------
template<int MODE>
__global__ void __launch_bounds__(128, 3)
moe_gemm(const float* __restrict__ A,     // MODE0: g_xr [T,H]; MODE1: g_c1p
         const float* __restrict__ Bt,    // MODE0: g_w1t [EF][H]; MODE1: g_w2t [H][EF]
         const float* __restrict__ probs, // [T,E]
         const int* __restrict__ idx,
         const int* __restrict__ cnt,
         float* __restrict__ Cout,        // MODE0: g_c1p; MODE1: g_y
         int K)                           // MODE0: HID; MODE1: FFN
{
    constexpr int BMT     = 64;
    constexpr int BNT     = 128;
    constexpr int THREADS = 128;
    constexpr int STAGES  = 3;
    constexpr int WM      = 32;           // warp tile M
    constexpr int MT      = 2;
    constexpr int NT      = 8;            // warp tile N = 64
    constexpr int A_BYTES = BMT * 128;    // 8192
    constexpr int B_BYTES = BNT * 128;    // 16384
    constexpr int STAGE   = A_BYTES + B_BYTES;   // 24576

    extern __shared__ __align__(128) char smem[];
    const uint32_t sb = smem_u32(smem);
    int* s_token = (int*)(smem + STAGES * STAGE);

    int e, tile, n0;
    if (MODE == 0) {
        tile = blockIdx.x;                // mtile fastest: B-slab L2 sharing
        e    = blockIdx.y >> 5;
        n0   = (blockIdx.y & 31) * BNT;
    } else {
        n0   = blockIdx.x * BNT;          // nb fastest: A-panel L2 sharing
        e    = blockIdx.y / TPE;
        tile = blockIdx.y % TPE;
    }
    if (tile * BMT >= cnt[e]) return;

    const int tid  = threadIdx.x;
    const int wid  = tid >> 5;
    const int lane = tid & 31;
    const int wm   = wid >> 1;            // 0..1
    const int wn   = wid & 1;             // 0..1
    const int row_base = e * CAP + tile * BMT;

    if (MODE == 0) {
        if (tid < BMT) s_token[tid] = idx[row_base + tid];
    }
    __syncthreads();

    const int CCH = K / 32;

    auto issue = [&](int c, int s) {
        uint32_t dA = sb + (uint32_t)s * STAGE;
        uint32_t dB = dA + A_BYTES;
        const int k0 = c * 32;
        #pragma unroll
        for (int i = 0; i < BMT * 8 / THREADS; i++) {   // A: 64 rows x 2 x 16B
            int id2 = tid + i * THREADS;
            int row = id2 >> 3, cb = (id2 & 7) << 4;
            const float* asrc;
            if (MODE == 0)
                asrc = A + (size_t)s_token[row] * K + k0 + (cb >> 2);
            else
                asrc = A + (size_t)(row_base + row) * K + k0 + (cb >> 2);
            cpa16(dA + sw128((uint32_t)(row * 128 + cb)), asrc);
        }
        #pragma unroll
        for (int i = 0; i < BNT * 8 / THREADS; i++) {   // B: 128 rows K-contig
            int id2 = tid + i * THREADS;
            int row = id2 >> 3, cb = (id2 & 7) << 4;
            const float* bsrc;
            if (MODE == 0)   // w1t rows e*F + n, stride K (=HID)
                bsrc = Bt + (size_t)(e * FFN + n0 + row) * K + k0 + (cb >> 2);
            else             // w2t rows n (stride EF), expert cols e*F + k
                bsrc = Bt + (size_t)(n0 + row) * EF + e * FFN + k0 + (cb >> 2);
            cpa16(dB + sw128((uint32_t)(row * 128 + cb)), bsrc);
        }
    };

    // prologue: stages 0,1
    #pragma unroll
    for (int s = 0; s < STAGES - 1; s++) {
        issue(s, s);
        asm volatile("cp.async.commit_group;" ::: "memory");
    }

    float acc[MT][NT][4];
    #pragma unroll
    for (int mt = 0; mt < MT; mt++)
        #pragma unroll
        for (int nt = 0; nt < NT; nt++)
            #pragma unroll
            for (int i = 0; i < 4; i++) acc[mt][nt][i] = 0.0f;

    const int g = lane >> 3, r = lane & 7;

    #pragma unroll 1
    for (int c = 0; c < CCH; c++) {
        // commits so far = 2 + c; allow 1 pending -> chunk c resident
        asm volatile("cp.async.wait_group 1;" ::: "memory");
        __syncthreads();
        // buffer (c+2)%3 == (c-1)%3: its readers finished before the barrier
        if (c + STAGES - 1 < CCH) issue(c + STAGES - 1, (c + STAGES - 1) % STAGES);
        asm volatile("cp.async.commit_group;" ::: "memory");  // uniform count

        const uint32_t sA  = sb + (uint32_t)(c % STAGES) * STAGE;
        const uint32_t sBm = sA + A_BYTES;

        #pragma unroll
        for (int ks = 0; ks < 4; ks++) {
            uint32_t bf[NT * 2];
            #pragma unroll
            for (int p = 0; p < NT / 2; p++) {
                int brow = wn * 64 + p * 16 + ((g >> 1) << 3) + r;
                int bcol = ks * 32 + ((g & 1) << 4);
                ldsm4(&bf[4 * p], sBm + sw128((uint32_t)(brow * 128 + bcol)));
            }
            uint32_t af[2][4];
            {
                int arow = wm * WM + ((g & 1) << 3) + r;
                int acol = ks * 32 + ((g >> 1) << 4);
                ldsm4(af[0], sA + sw128((uint32_t)(arow * 128 + acol)));
            }
            #pragma unroll
            for (int mt = 0; mt < MT; mt++) {
                if (mt + 1 < MT) {
                    int arow = wm * WM + (mt + 1) * 16 + ((g & 1) << 3) + r;
                    int acol = ks * 32 + ((g >> 1) << 4);
                    ldsm4(af[(mt + 1) & 1], sA + sw128((uint32_t)(arow * 128 + acol)));
                }
                #pragma unroll
                for (int nt = 0; nt < NT; nt++)
                    mma8(acc[mt][nt], af[mt & 1], bf[nt * 2], bf[nt * 2 + 1]);
            }
        }
    }

    // ---------------- epilogue ----------------
    const int qr = lane >> 2, rm = lane & 3;
    const int ldc = (MODE == 0) ? FFN : HID;

    #pragma unroll
    for (int mt = 0; mt < MT; mt++) {
        const int lr0 = wm * WM + mt * 16 + qr;
        const int lr1 = lr0 + 8;
        float p0 = 1.0f, p1 = 1.0f;
        if (MODE == 0) {
            p0 = probs[s_token[lr0] * NEXP + e];
            p1 = probs[s_token[lr1] * NEXP + e];
        }
        #pragma unroll
        for (int nt = 0; nt < NT; nt++) {
            const int col = n0 + wn * 64 + nt * 8 + (rm << 1);
            float2 v0, v1;
            if (MODE == 0) {
                v0.x = to_tf32(gelu_exact(acc[mt][nt][0]) * p0);
                v0.y = to_tf32(gelu_exact(acc[mt][nt][1]) * p0);
                v1.x = to_tf32(gelu_exact(acc[mt][nt][2]) * p1);
                v1.y = to_tf32(gelu_exact(acc[mt][nt][3]) * p1);
            } else {
                v0.x = acc[mt][nt][0]; v0.y = acc[mt][nt][1];
                v1.x = acc[mt][nt][2]; v1.y = acc[mt][nt][3];
            }
            *(float2*)&Cout[(size_t)(row_base + lr0) * ldc + col] = v0;
            *(float2*)&Cout[(size_t)(row_base + lr1) * ldc + col] = v1;
        }
    }
}

// ---------------------------------------------------------------------------
// launch
// ---------------------------------------------------------------------------
extern "C" void kernel_launch(void* const* d_in, const int* in_sizes, int n_in,
                              void* d_out, int out_size) {
    const float* x     = (const float*)d_in[0];   // hidden_states [T,H]
    const float* resid = (const float*)d_in[1];   // mlp_residual  [T,H]
    const float* probs = (const float*)d_in[2];   // probs [T,E] (masked)
    // d_in[3] = routing_map (unused: probs>0 is the same mask, dtype-safe)
    const float* w1    = (const float*)d_in[4];   // [E,H,F]
    const float* w2    = (const float*)d_in[5];   // [E,F,H]
    float* out = (float*)d_out;

    float *xr, *w1t, *w2t, *c1p, *yp;
    int *idxp, *slotp, *cntp;
    cudaGetSymbolAddress((void**)&xr,   g_xr);
    cudaGetSymbolAddress((void**)&w1t,  g_w1t);
    cudaGetSymbolAddress((void**)&w2t,  g_w2t);
    cudaGetSymbolAddress((void**)&c1p,  g_c1p);
    cudaGetSymbolAddress((void**)&yp,   g_y);
    cudaGetSymbolAddress((void**)&idxp, g_idx);
    cudaGetSymbolAddress((void**)&slotp, g_slot);
    cudaGetSymbolAddress((void**)&cntp, g_cnt);

    // both GEMMs: 64x128 CTA, 3-stage, occ 3.
    // smem = 3*24576 + 256 = 73984; x3 CTAs = 221952 <= 228KB.
    constexpr int SMEM = 3 * (64 * 128 + 128 * 128) + 64 * 4;
    auto* k1 = moe_gemm<0>;
    auto* k2 = moe_gemm<1>;
    cudaFuncSetAttribute(k1, cudaFuncAttributeMaxDynamicSharedMemorySize, SMEM);
    cudaFuncSetAttribute(k2, cudaFuncAttributeMaxDynamicSharedMemorySize, SMEM);

    // merged prep + routing (cnt==0 at entry: static init / zeroed by combine)
    prep<<<10248, 256>>>(w1, w1t, w2, w2t, x, xr, probs, idxp, slotp, cntp);

    // routed GEMM1: gather X -> gelu*probs -> c1p.  grid (33, 128) x 128T
    k1<<<dim3(TPE, NEXP * (FFN / 128)), 128, SMEM>>>(
        xr, w1t, probs, idxp, cntp, c1p, HID);
    // routed GEMM2: c1p @ W2[e] -> y.               grid (8, 132) x 128T
    k2<<<dim3(HID / 128, NEXP * TPE), 128, SMEM>>>(
        c1p, w2t, probs, idxp, cntp, yp, FFN);
    // combine: out = resid + sum_topk y; also resets cnt for next replay
    combine<<<T_TOK, 256>>>(yp, probs, slotp, resid, out, cntp);
}